// round 1
// baseline (speedup 1.0000x reference)
#include <cuda_runtime.h>
#include <math.h>

#define MAXK  5
#define CDIM  512
#define HWDIM 32768
#define TB    8            // spatial positions per CTA
#define NTHR  512
#define SMEM_BYTES (MAXK * CDIM * TB * 4)   // 81920 B -> 2 CTAs/SM

__global__ __launch_bounds__(NTHR, 2)
void attfusion_kernel(const float* __restrict__ x,
                      const int* __restrict__ record_len,
                      float* __restrict__ out) {
    extern __shared__ float s[];                 // s[k][c][bl]  (bl stride 1, row = TB)
    __shared__ float part[8][TB][MAXK];          // per-warp partial dots
    __shared__ float wgt[TB][MAXK];              // softmax weights

    const int t  = threadIdx.x;
    const int b0 = blockIdx.x * TB;
    int rl = *record_len;
    rl = rl < 0 ? 0 : (rl > MAXK ? MAXK : rl);

    if (rl == 0) {
        // all masked -> softmax NaN -> nan_to_num -> zeros
        const int bl = t & (TB - 1);
        const int cg = t >> 3;                   // 0..63
        #pragma unroll
        for (int it = 0; it < CDIM / 64; ++it) {
            int c = cg + 64 * it;
            out[(size_t)c * HWDIM + b0 + bl] = 0.0f;
        }
        return;
    }

    // ---------------- Load phase: x[k, c, b0..b0+7] -> s[(k*512+c)*8 + bl]
    for (int k = 0; k < rl; ++k) {
        const float* xk = x + (size_t)k * CDIM * HWDIM + b0;
        #pragma unroll
        for (int i = 0; i < 2; ++i) {
            int idx = t + NTHR * i;              // 0..1023
            int c   = idx >> 1;
            int q   = (idx & 1) << 2;            // 0 or 4
            float4 v = *(const float4*)(xk + (size_t)c * HWDIM + q);
            *(float4*)(s + (k * CDIM + c) * TB + q) = v;
        }
    }
    __syncthreads();

    // ---------------- Dot phase: warps 0..7, conflict-free lane remap
    {
        const int w    = t >> 5;
        const int lane = t & 31;
        if (w < 8) {
            const int bl   = lane & 7;           // spatial position
            const int cseg = lane >> 3;          // 0..3
            float acc[MAXK];
            #pragma unroll
            for (int k = 0; k < MAXK; ++k) acc[k] = 0.0f;

            const int cbase = w * 64 + cseg;
            #pragma unroll
            for (int i = 0; i < 16; ++i) {
                int c = cbase + 4 * i;
                float t0 = s[c * TB + bl];
                acc[0] += t0 * t0;
                #pragma unroll
                for (int k = 1; k < MAXK; ++k)
                    if (k < rl) acc[k] += t0 * s[(k * CDIM + c) * TB + bl];
            }
            // combine lanes {l, l^8, l^16, l^24} (same bl, different cseg)
            #pragma unroll
            for (int k = 0; k < MAXK; ++k) {
                acc[k] += __shfl_xor_sync(0xffffffffu, acc[k], 8);
                acc[k] += __shfl_xor_sync(0xffffffffu, acc[k], 16);
            }
            if (lane < 8) {
                #pragma unroll
                for (int k = 0; k < MAXK; ++k) part[w][lane][k] = acc[k];
            }
        }
    }
    __syncthreads();

    // ---------------- Softmax (threads 0..7, one per bl)
    if (t < TB) {
        const float scale = 0.044194173824159216f;   // 1/sqrt(512)
        float d[MAXK];
        #pragma unroll
        for (int k = 0; k < MAXK; ++k) {
            float sum = 0.0f;
            #pragma unroll
            for (int w = 0; w < 8; ++w) sum += part[w][t][k];
            d[k] = sum * scale;
        }
        float m = -INFINITY;
        #pragma unroll
        for (int k = 0; k < MAXK; ++k)
            if (k < rl) m = fmaxf(m, d[k]);
        float e[MAXK], esum = 0.0f;
        #pragma unroll
        for (int k = 0; k < MAXK; ++k) {
            e[k] = (k < rl) ? expf(d[k] - m) : 0.0f;
            esum += e[k];
        }
        float inv = 1.0f / esum;
        #pragma unroll
        for (int k = 0; k < MAXK; ++k) wgt[t][k] = e[k] * inv;
    }
    __syncthreads();

    // ---------------- Output phase: out[c*HW + b0 + bl] = sum_k w_k * s[k][c][bl]
    {
        const int bl = t & (TB - 1);
        const int cg = t >> 3;                   // 0..63
        float wl[MAXK];
        #pragma unroll
        for (int k = 0; k < MAXK; ++k) wl[k] = wgt[bl][k];
        #pragma unroll
        for (int it = 0; it < CDIM / 64; ++it) {
            int c = cg + 64 * it;
            float v = 0.0f;
            #pragma unroll
            for (int k = 0; k < MAXK; ++k)
                if (k < rl) v += wl[k] * s[(k * CDIM + c) * TB + bl];
            out[(size_t)c * HWDIM + b0 + bl] = v;
        }
    }
}

extern "C" void kernel_launch(void* const* d_in, const int* in_sizes, int n_in,
                              void* d_out, int out_size) {
    const float* x  = (const float*)d_in[0];
    const int* rl   = (const int*)d_in[1];
    float* out      = (float*)d_out;
    cudaFuncSetAttribute(attfusion_kernel,
                         cudaFuncAttributeMaxDynamicSharedMemorySize, SMEM_BYTES);
    attfusion_kernel<<<HWDIM / TB, NTHR, SMEM_BYTES>>>(x, rl, out);
}

// round 2
// speedup vs baseline: 1.2805x; 1.2805x over previous
#include <cuda_runtime.h>
#include <math.h>

#define MAXK  5
#define CDIM  512
#define HWDIM 32768
#define TB    8            // spatial positions per CTA
#define NTHR  512
#define SMEM_BYTES (MAXK * CDIM * TB * 4)   // 81920 B -> 2 CTAs/SM

__device__ __forceinline__ void cp_async16(float* smem_dst, const float* gsrc) {
    unsigned int saddr = (unsigned int)__cvta_generic_to_shared(smem_dst);
    asm volatile("cp.async.cg.shared.global [%0], [%1], 16;\n"
                 :: "r"(saddr), "l"(gsrc));
}

__global__ __launch_bounds__(NTHR, 2)
void attfusion_kernel(const float* __restrict__ x,
                      const int* __restrict__ record_len,
                      float* __restrict__ out) {
    extern __shared__ float s[];                 // s[k][c][bl]  (bl stride 1)
    __shared__ float part[8][TB][MAXK];          // per-warp partial dots
    __shared__ float wgt[TB][MAXK];              // softmax weights

    const int t  = threadIdx.x;
    const int b0 = blockIdx.x * TB;
    int rl = *record_len;
    rl = rl < 0 ? 0 : (rl > MAXK ? MAXK : rl);

    if (rl == 0) {
        const int bl = t & (TB - 1);
        const int cg = t >> 3;
        #pragma unroll
        for (int it = 0; it < CDIM / 64; ++it) {
            int c = cg + 64 * it;
            out[(size_t)c * HWDIM + b0 + bl] = 0.0f;
        }
        return;
    }

    // ---------------- Load phase: cp.async, fully batched (register-free)
    {
        const int c0 = t >> 1;                   // slot 0: c in [0,256)
        const int q  = (t & 1) << 2;             // 0 or 4
        #pragma unroll
        for (int k = 0; k < MAXK; ++k) {
            if (k < rl) {
                const float* xk = x + (size_t)k * CDIM * HWDIM + b0 + q;
                cp_async16(s + (k * CDIM + c0)       * TB + q, xk + (size_t)c0 * HWDIM);
                cp_async16(s + (k * CDIM + c0 + 256) * TB + q, xk + (size_t)(c0 + 256) * HWDIM);
            }
        }
        asm volatile("cp.async.commit_group;\n" ::: "memory");
        asm volatile("cp.async.wait_group 0;\n" ::: "memory");
    }
    __syncthreads();

    // ---------------- Dot phase: warps 0..7, conflict-free lane remap
    {
        const int w    = t >> 5;
        const int lane = t & 31;
        if (w < 8) {
            const int bl   = lane & 7;           // spatial position
            const int cseg = lane >> 3;          // 0..3
            float acc[MAXK];
            #pragma unroll
            for (int k = 0; k < MAXK; ++k) acc[k] = 0.0f;

            const int cbase = w * 64 + cseg;
            #pragma unroll
            for (int i = 0; i < 16; ++i) {
                int c = cbase + 4 * i;
                float t0 = s[c * TB + bl];
                acc[0] += t0 * t0;
                #pragma unroll
                for (int k = 1; k < MAXK; ++k)
                    if (k < rl) acc[k] += t0 * s[(k * CDIM + c) * TB + bl];
            }
            #pragma unroll
            for (int k = 0; k < MAXK; ++k) {
                acc[k] += __shfl_xor_sync(0xffffffffu, acc[k], 8);
                acc[k] += __shfl_xor_sync(0xffffffffu, acc[k], 16);
            }
            if (lane < 8) {
                #pragma unroll
                for (int k = 0; k < MAXK; ++k) part[w][lane][k] = acc[k];
            }
        }
    }
    __syncthreads();

    // ---------------- Softmax (threads 0..7, one per bl)
    if (t < TB) {
        const float scale = 0.044194173824159216f;   // 1/sqrt(512)
        float d[MAXK];
        #pragma unroll
        for (int k = 0; k < MAXK; ++k) {
            float sum = 0.0f;
            #pragma unroll
            for (int w = 0; w < 8; ++w) sum += part[w][t][k];
            d[k] = sum * scale;
        }
        float m = -INFINITY;
        #pragma unroll
        for (int k = 0; k < MAXK; ++k)
            if (k < rl) m = fmaxf(m, d[k]);
        float e[MAXK], esum = 0.0f;
        #pragma unroll
        for (int k = 0; k < MAXK; ++k) {
            e[k] = (k < rl) ? expf(d[k] - m) : 0.0f;
            esum += e[k];
        }
        float inv = 1.0f / esum;
        #pragma unroll
        for (int k = 0; k < MAXK; ++k) wgt[t][k] = e[k] * inv;
    }
    __syncthreads();

    // ---------------- Output phase: float4 over b-quads
    // thread t handles (c = t>>1, q = (t&1)*4) and (c+256, q)
    {
        const int c0 = t >> 1;
        const int qb = (t & 1) << 2;             // b-quad base: 0 or 4
        float w4[MAXK][4];
        #pragma unroll
        for (int k = 0; k < MAXK; ++k)
            #pragma unroll
            for (int j = 0; j < 4; ++j)
                w4[k][j] = wgt[qb + j][k];

        #pragma unroll
        for (int slot = 0; slot < 2; ++slot) {
            int c = c0 + 256 * slot;
            float4 v = make_float4(0.f, 0.f, 0.f, 0.f);
            #pragma unroll
            for (int k = 0; k < MAXK; ++k) {
                if (k < rl) {
                    float4 tk = *(const float4*)(s + (k * CDIM + c) * TB + qb);
                    v.x += w4[k][0] * tk.x;
                    v.y += w4[k][1] * tk.y;
                    v.z += w4[k][2] * tk.z;
                    v.w += w4[k][3] * tk.w;
                }
            }
            *(float4*)(out + (size_t)c * HWDIM + b0 + qb) = v;
        }
    }
}

extern "C" void kernel_launch(void* const* d_in, const int* in_sizes, int n_in,
                              void* d_out, int out_size) {
    const float* x  = (const float*)d_in[0];
    const int* rl   = (const int*)d_in[1];
    float* out      = (float*)d_out;
    cudaFuncSetAttribute(attfusion_kernel,
                         cudaFuncAttributeMaxDynamicSharedMemorySize, SMEM_BYTES);
    attfusion_kernel<<<HWDIM / TB, NTHR, SMEM_BYTES>>>(x, rl, out);
}